// round 13
// baseline (speedup 1.0000x reference)
#include <cuda_runtime.h>
#include <math.h>

// Shapes (compile-time constants)
#define BB   64
#define LL   4096
#define DKK  128
#define DVV  128
#define HH   4
#define DKL_ 64
#define DVL_ 128
#define RR   128

#define NCHUNK 32
#define LCHUNK (LL / NCHUNK)   // 128

__device__ float g_q[HH * DKK];                        // q[h][d]   (2 KB)
__device__ float g_M[HH * DVV * RR];                   // M[h][e][r] (256 KB)
__device__ float4 g_s[(size_t)BB * LL];                // scores [b][l][h]  (4 MB)
__device__ float g_red[BB * HH * 2];                   // {max, 1/sum}
__device__ float g_tp[(size_t)NCHUNK * BB * HH * DVV]; // partial t (4 MB)
__device__ int   g_mask_mode;                          // 0=int32, 1=float32, 2=uint8

#define SCALE_QK 0.08838834764831845f   // 1/sqrt(128)

// ---------------------------------------------------------------------------
// Kernel 0: detect mask dtype from the raw buffer. Deterministic.
// int32 bool:   every 32-bit word is 0 or 1.
// float32 bool: every 32-bit word is 0 or 0x3F800000 (1.0f).
// uint8 bool:   neither word pattern holds (bytes 0/1 packed 4-per-word).
// ---------------------------------------------------------------------------
__global__ void k_detect(const unsigned int* __restrict__ m) {
    int not01 = 0, notf = 0;
    for (int i = 0; i < 1024; i++) {
        unsigned int w = m[i];
        if (w != 0u && w != 1u) not01++;
        if (w != 0u && w != 0x3F800000u) notf++;
    }
    g_mask_mode = (not01 == 0) ? 0 : ((notf == 0) ? 1 : 2);
}

// ---------------------------------------------------------------------------
// Kernel 1: q[h][d] = sum_k Wk[d,h,k] * Wq[h,k]
// ---------------------------------------------------------------------------
__global__ void k_prep_q(const float* __restrict__ Wq, const float* __restrict__ Wk) {
    int t = threadIdx.x;              // 512 threads: t = h*DKK + d
    int h = t / DKK, d = t % DKK;
    const float* wk = Wk + (size_t)d * HH * DKL_ + h * DKL_;
    const float* wq = Wq + h * DKL_;
    float s = 0.f;
#pragma unroll
    for (int k = 0; k < DKL_; k++) s += wk[k] * wq[k];
    g_q[h * DKK + d] = s;
}

// ---------------------------------------------------------------------------
// Kernel 2: M[h][e][r] = sum_v Wv[e,h,v] * Wo[h,v,r]
// grid: H*DV blocks, 128 threads (r)
// ---------------------------------------------------------------------------
__global__ void k_prep_M(const float* __restrict__ Wv, const float* __restrict__ Wo) {
    int he = blockIdx.x;
    int h = he / DVV, e = he % DVV;
    int r = threadIdx.x;
    __shared__ float wv[DVL_];
    wv[r] = Wv[(size_t)e * HH * DVL_ + h * DVL_ + r];
    __syncthreads();
    const float* wo = Wo + (size_t)h * DVL_ * RR + r;
    float s = 0.f;
#pragma unroll 8
    for (int v = 0; v < DVL_; v++) s += wv[v] * wo[(size_t)v * RR];
    g_M[(size_t)he * RR + r] = s;
}

// ---------------------------------------------------------------------------
// Kernel 3: scores. One warp per (b,l) row; float4 loads of K row.
// g_s[b*LL+l] = {s_h0, s_h1, s_h2, s_h3}; masked rows get -3e38.
// 256 threads/block = 8 rows/block.
// ---------------------------------------------------------------------------
__global__ void k_scores(const float* __restrict__ K, const void* __restrict__ mask) {
    __shared__ float shq[HH * DKK];
    int tid = threadIdx.x;
    shq[tid]       = g_q[tid];
    shq[tid + 256] = g_q[tid + 256];
    __syncthreads();

    int warp = tid >> 5, lane = tid & 31;
    long long row = (long long)blockIdx.x * 8 + warp;     // row = b*LL + l

    float4 kv = *(const float4*)(K + row * DKK + lane * 4);
    float p0, p1, p2, p3;
    {
        float4 q0 = *(const float4*)(shq + 0 * DKK + lane * 4);
        float4 q1 = *(const float4*)(shq + 1 * DKK + lane * 4);
        float4 q2 = *(const float4*)(shq + 2 * DKK + lane * 4);
        float4 q3 = *(const float4*)(shq + 3 * DKK + lane * 4);
        p0 = kv.x * q0.x + kv.y * q0.y + kv.z * q0.z + kv.w * q0.w;
        p1 = kv.x * q1.x + kv.y * q1.y + kv.z * q1.z + kv.w * q1.w;
        p2 = kv.x * q2.x + kv.y * q2.y + kv.z * q2.z + kv.w * q2.w;
        p3 = kv.x * q3.x + kv.y * q3.y + kv.z * q3.z + kv.w * q3.w;
    }
#pragma unroll
    for (int off = 16; off; off >>= 1) {
        p0 += __shfl_xor_sync(0xffffffffu, p0, off);
        p1 += __shfl_xor_sync(0xffffffffu, p1, off);
        p2 += __shfl_xor_sync(0xffffffffu, p2, off);
        p3 += __shfl_xor_sync(0xffffffffu, p3, off);
    }
    if (lane == 0) {
        int mode = g_mask_mode;
        bool m;
        if (mode == 0)      m = ((const int*)mask)[row] != 0;
        else if (mode == 1) m = ((const float*)mask)[row] != 0.0f;
        else                m = ((const unsigned char*)mask)[row] != 0;
        float4 s4;
        s4.x = m ? -3.0e38f : SCALE_QK * p0;
        s4.y = m ? -3.0e38f : SCALE_QK * p1;
        s4.z = m ? -3.0e38f : SCALE_QK * p2;
        s4.w = m ? -3.0e38f : SCALE_QK * p3;
        g_s[row] = s4;
    }
}

// ---------------------------------------------------------------------------
// Kernel 4: per-b row-max and inverse sum of exp for all 4 heads at once.
// One block per b. 256 threads, 16 float4 each, register-resident between
// the two reductions.
// ---------------------------------------------------------------------------
__global__ void k_redmax() {
    int b = blockIdx.x;
    int tid = threadIdx.x;
    const float4* s = g_s + (size_t)b * LL;
    float4 v[16];
    float4 m = make_float4(-3.4e38f, -3.4e38f, -3.4e38f, -3.4e38f);
#pragma unroll
    for (int i = 0; i < 16; i++) {
        v[i] = s[tid + i * 256];
        m.x = fmaxf(m.x, v[i].x);
        m.y = fmaxf(m.y, v[i].y);
        m.z = fmaxf(m.z, v[i].z);
        m.w = fmaxf(m.w, v[i].w);
    }
    __shared__ float4 sh[256];
    sh[tid] = m;
    __syncthreads();
    for (int off = 128; off; off >>= 1) {
        if (tid < off) {
            float4 o = sh[tid + off];
            sh[tid].x = fmaxf(sh[tid].x, o.x);
            sh[tid].y = fmaxf(sh[tid].y, o.y);
            sh[tid].z = fmaxf(sh[tid].z, o.z);
            sh[tid].w = fmaxf(sh[tid].w, o.w);
        }
        __syncthreads();
    }
    m = sh[0];
    __syncthreads();
    float4 sum = make_float4(0.f, 0.f, 0.f, 0.f);
#pragma unroll
    for (int i = 0; i < 16; i++) {
        sum.x += __expf(v[i].x - m.x);
        sum.y += __expf(v[i].y - m.y);
        sum.z += __expf(v[i].z - m.z);
        sum.w += __expf(v[i].w - m.w);
    }
    sh[tid] = sum;
    __syncthreads();
    for (int off = 128; off; off >>= 1) {
        if (tid < off) {
            float4 o = sh[tid + off];
            sh[tid].x += o.x;
            sh[tid].y += o.y;
            sh[tid].z += o.z;
            sh[tid].w += o.w;
        }
        __syncthreads();
    }
    if (tid == 0) {
        float4 s0 = sh[0];
        g_red[(b * HH + 0) * 2 + 0] = m.x;  g_red[(b * HH + 0) * 2 + 1] = 1.0f / s0.x;
        g_red[(b * HH + 1) * 2 + 0] = m.y;  g_red[(b * HH + 1) * 2 + 1] = 1.0f / s0.y;
        g_red[(b * HH + 2) * 2 + 0] = m.z;  g_red[(b * HH + 2) * 2 + 1] = 1.0f / s0.z;
        g_red[(b * HH + 3) * 2 + 0] = m.w;  g_red[(b * HH + 3) * 2 + 1] = 1.0f / s0.w;
    }
}

// ---------------------------------------------------------------------------
// Kernel 5: V accumulate. grid (chunk=32, b=64), 128 threads (e).
// Partial t[c][b][h][e] = sum_{l in chunk} exp(s - max) * V[b,l,e].
// Weights for all 4 heads come from one float4 per l. No atomics.
// ---------------------------------------------------------------------------
__global__ void k_vacc(const float* __restrict__ V) {
    int c = blockIdx.x, b = blockIdx.y;
    int tid = threadIdx.x;
    int l0 = c * LCHUNK;

    __shared__ float4 w[LCHUNK];
    {
        float m0 = g_red[(b * HH + 0) * 2];
        float m1 = g_red[(b * HH + 1) * 2];
        float m2 = g_red[(b * HH + 2) * 2];
        float m3 = g_red[(b * HH + 3) * 2];
        float4 s4 = g_s[(size_t)b * LL + l0 + tid];
        w[tid] = make_float4(__expf(s4.x - m0), __expf(s4.y - m1),
                             __expf(s4.z - m2), __expf(s4.w - m3));
    }
    __syncthreads();

    float a0 = 0.f, a1 = 0.f, a2 = 0.f, a3 = 0.f;
    const float* Vb = V + ((size_t)b * LL + l0) * DVV + tid;
#pragma unroll 16
    for (int l = 0; l < LCHUNK; l++) {
        float v = Vb[(size_t)l * DVV];
        float4 wl = w[l];
        a0 += wl.x * v;
        a1 += wl.y * v;
        a2 += wl.z * v;
        a3 += wl.w * v;
    }
    float* tp = g_tp + (size_t)(c * BB + b) * HH * DVV + tid;
    tp[0 * DVV] = a0;
    tp[1 * DVV] = a1;
    tp[2 * DVV] = a2;
    tp[3 * DVV] = a3;
}

// ---------------------------------------------------------------------------
// Kernel 6: reduce chunk partials, normalize, and contract with M.
// out[b][r] = (1/L) * sum_{h,e} (inv_sum[b,h] * t[b,h,e]) * M[h,e,r]
// grid: 64 blocks (b), 128 threads (r).
// ---------------------------------------------------------------------------
__global__ void k_out(float* __restrict__ out) {
    int b = blockIdx.x;
    int tid = threadIdx.x;
    __shared__ float ts[HH * DVV];   // 512
#pragma unroll
    for (int i = 0; i < 4; i++) {
        int idx = i * 128 + tid;
        int h = idx >> 7;
        float s = 0.f;
#pragma unroll 8
        for (int c = 0; c < NCHUNK; c++)
            s += g_tp[(size_t)(c * BB + b) * HH * DVV + idx];
        ts[idx] = s * g_red[(b * HH + h) * 2 + 1];
    }
    __syncthreads();
    float acc = 0.f;
#pragma unroll 8
    for (int he = 0; he < HH * DVV; he++)
        acc += ts[he] * g_M[(size_t)he * RR + tid];
    out[b * RR + tid] = acc * (1.0f / LL);
}

// ---------------------------------------------------------------------------
extern "C" void kernel_launch(void* const* d_in, const int* in_sizes, int n_in,
                              void* d_out, int out_size) {
    const float* K  = (const float*)d_in[0];
    const float* V  = (const float*)d_in[1];
    const void*  mk = d_in[2];
    const float* Wq = (const float*)d_in[3];
    const float* Wk = (const float*)d_in[4];
    const float* Wv = (const float*)d_in[5];
    const float* Wo = (const float*)d_in[6];
    float* out = (float*)d_out;

    k_detect<<<1, 1>>>((const unsigned int*)mk);
    k_prep_q<<<1, 512>>>(Wq, Wk);
    k_prep_M<<<HH * DVV, 128>>>(Wv, Wo);
    k_scores<<<BB * LL / 8, 256>>>(K, mk);
    k_redmax<<<BB, 256>>>();
    k_vacc<<<dim3(NCHUNK, BB), 128>>>(V);
    k_out<<<BB, 128>>>(out);
}

// round 14
// speedup vs baseline: 1.1841x; 1.1841x over previous
#include <cuda_runtime.h>
#include <math.h>

#define BB   64
#define LL   4096
#define DKK  128
#define DVV  128
#define HH   4
#define DKL_ 64
#define DVL_ 128
#define RR   128
#define NCHUNK 32
#define LCHUNK 128
#define NPART 4

#define SCALE_QK 0.08838834764831845f   // 1/sqrt(128)

__device__ float    g_q[HH * DKK];
__device__ float    g_M[HH * DVV * RR];
__device__ float4   g_s[(size_t)BB * LL];            // scores [b][l][h]
__device__ unsigned g_maxbits[BB * HH];              // encoded running max
__device__ float    g_psum[NPART * BB * HH];         // partial sum-exp
__device__ float    g_tp[(size_t)NCHUNK * BB * HH * DVV];
__device__ int      g_mask_mode;                     // 0=int32 1=float32 2=uint8

// Monotonic float<->uint encoding so unsigned atomicMax == float max.
__device__ __forceinline__ unsigned encf(float f) {
    unsigned u = __float_as_uint(f);
    return (u & 0x80000000u) ? ~u : (u | 0x80000000u);
}
__device__ __forceinline__ float decf(unsigned e) {
    return (e & 0x80000000u) ? __uint_as_float(e ^ 0x80000000u)
                             : __uint_as_float(~e);
}

// ---------------------------------------------------------------------------
// Kernel 0: reset per-(b,h) max slots; detect mask dtype. Deterministic.
// ---------------------------------------------------------------------------
__global__ void k_init(const unsigned int* __restrict__ m) {
    int tid = threadIdx.x;
    g_maxbits[tid] = 0u;   // encodes below any real float
    if (tid == 0) {
        int not01 = 0, notf = 0;
        for (int i = 0; i < 1024; i++) {
            unsigned int w = m[i];
            if (w != 0u && w != 1u) not01++;
            if (w != 0u && w != 0x3F800000u) notf++;
        }
        g_mask_mode = (not01 == 0) ? 0 : ((notf == 0) ? 1 : 2);
    }
}

// ---------------------------------------------------------------------------
// Kernel 1: q[h][d] = sum_k Wk[d,h,k] * Wq[h,k]
// ---------------------------------------------------------------------------
__global__ void k_prep_q(const float* __restrict__ Wq, const float* __restrict__ Wk) {
    int t = threadIdx.x;
    int h = t / DKK, d = t % DKK;
    const float* wk = Wk + (size_t)d * HH * DKL_ + h * DKL_;
    const float* wq = Wq + h * DKL_;
    float s = 0.f;
#pragma unroll
    for (int k = 0; k < DKL_; k++) s += wk[k] * wq[k];
    g_q[h * DKK + d] = s;
}

// ---------------------------------------------------------------------------
// Kernel 2: M[h][e][r] = sum_v Wv[e,h,v] * Wo[h,v,r]
// ---------------------------------------------------------------------------
__global__ void k_prep_M(const float* __restrict__ Wv, const float* __restrict__ Wo) {
    int he = blockIdx.x;
    int h = he / DVV, e = he % DVV;
    int r = threadIdx.x;
    __shared__ float wv[DVL_];
    wv[r] = Wv[(size_t)e * HH * DVL_ + h * DVL_ + r];
    __syncthreads();
    const float* wo = Wo + (size_t)h * DVL_ * RR + r;
    float s = 0.f;
#pragma unroll 8
    for (int v = 0; v < DVL_; v++) s += wv[v] * wo[(size_t)v * RR];
    g_M[(size_t)he * RR + r] = s;
}

// ---------------------------------------------------------------------------
// Kernel 3: scores. 256 threads = 8 warps, 2 rows/warp (16 lanes each).
// q is register-resident (no per-row LDS). Block-level max -> atomicMax.
// grid = BB*LL/16 = 16384; 256 blocks per batch b.
// ---------------------------------------------------------------------------
__global__ void k_scores(const float* __restrict__ K, const void* __restrict__ mask) {
    __shared__ float shq[HH * DKK];
    __shared__ float smax[8][HH];
    int tid = threadIdx.x;
    shq[tid]       = g_q[tid];
    shq[tid + 256] = g_q[tid + 256];
    __syncthreads();

    int warp = tid >> 5, lane = tid & 31, half = lane >> 4, sub = lane & 15;
    // q registers: d-slice {sub*4..+3} and {64+sub*4..+3} for all 4 heads
    float4 qa[HH], qb[HH];
#pragma unroll
    for (int h = 0; h < HH; h++) {
        qa[h] = *(const float4*)(shq + h * DKK + sub * 4);
        qb[h] = *(const float4*)(shq + h * DKK + 64 + sub * 4);
    }

    long long row = (long long)blockIdx.x * 16 + warp * 2 + half;
    const float* Kr = K + (size_t)row * DKK;
    float4 a  = *(const float4*)(Kr + sub * 4);
    float4 bb = *(const float4*)(Kr + 64 + sub * 4);

    float p[HH];
#pragma unroll
    for (int h = 0; h < HH; h++) {
        p[h] = a.x * qa[h].x + a.y * qa[h].y + a.z * qa[h].z + a.w * qa[h].w
             + bb.x * qb[h].x + bb.y * qb[h].y + bb.z * qb[h].z + bb.w * qb[h].w;
    }
#pragma unroll
    for (int off = 8; off; off >>= 1) {
#pragma unroll
        for (int h = 0; h < HH; h++)
            p[h] += __shfl_xor_sync(0xffffffffu, p[h], off);
    }

    float4 s4 = make_float4(-3.0e38f, -3.0e38f, -3.0e38f, -3.0e38f);
    if (sub == 0) {
        int mode = g_mask_mode;
        bool m;
        if (mode == 0)      m = ((const int*)mask)[row] != 0;
        else if (mode == 1) m = ((const float*)mask)[row] != 0.0f;
        else                m = ((const unsigned char*)mask)[row] != 0;
        if (!m) {
            s4.x = SCALE_QK * p[0];
            s4.y = SCALE_QK * p[1];
            s4.z = SCALE_QK * p[2];
            s4.w = SCALE_QK * p[3];
        }
        g_s[row] = s4;
    }
    // warp max over its two rows (lanes 0 and 16 hold real s4)
    float4 so;
    so.x = __shfl_xor_sync(0xffffffffu, s4.x, 16);
    so.y = __shfl_xor_sync(0xffffffffu, s4.y, 16);
    so.z = __shfl_xor_sync(0xffffffffu, s4.z, 16);
    so.w = __shfl_xor_sync(0xffffffffu, s4.w, 16);
    if (lane == 0) {
        smax[warp][0] = fmaxf(s4.x, so.x);
        smax[warp][1] = fmaxf(s4.y, so.y);
        smax[warp][2] = fmaxf(s4.z, so.z);
        smax[warp][3] = fmaxf(s4.w, so.w);
    }
    __syncthreads();
    if (tid < HH) {
        float m = smax[0][tid];
#pragma unroll
        for (int w = 1; w < 8; w++) m = fmaxf(m, smax[w][tid]);
        int b = blockIdx.x >> 8;
        atomicMax(&g_maxbits[b * HH + tid], encf(m));
    }
}

// ---------------------------------------------------------------------------
// Kernel 4: partial sum of exp(s - max). grid (NPART, BB), 256 threads.
// Each block covers 1024 l's. Deterministic (fixed merge order in k_out).
// ---------------------------------------------------------------------------
__global__ void k_sumexp() {
    int p = blockIdx.x, b = blockIdx.y;
    int tid = threadIdx.x;
    float4 m4;
    m4.x = decf(g_maxbits[b * HH + 0]);
    m4.y = decf(g_maxbits[b * HH + 1]);
    m4.z = decf(g_maxbits[b * HH + 2]);
    m4.w = decf(g_maxbits[b * HH + 3]);
    const float4* s = g_s + (size_t)b * LL + p * 1024;
    float4 acc = make_float4(0.f, 0.f, 0.f, 0.f);
#pragma unroll
    for (int i = 0; i < 4; i++) {
        float4 v = s[tid + i * 256];
        acc.x += __expf(v.x - m4.x);
        acc.y += __expf(v.y - m4.y);
        acc.z += __expf(v.z - m4.z);
        acc.w += __expf(v.w - m4.w);
    }
    __shared__ float4 sh[256];
    sh[tid] = acc;
    __syncthreads();
    for (int off = 128; off; off >>= 1) {
        if (tid < off) {
            float4 o = sh[tid + off];
            sh[tid].x += o.x; sh[tid].y += o.y;
            sh[tid].z += o.z; sh[tid].w += o.w;
        }
        __syncthreads();
    }
    if (tid == 0) {
        float4 t = sh[0];
        g_psum[(p * BB + b) * HH + 0] = t.x;
        g_psum[(p * BB + b) * HH + 1] = t.y;
        g_psum[(p * BB + b) * HH + 2] = t.z;
        g_psum[(p * BB + b) * HH + 3] = t.w;
    }
}

// ---------------------------------------------------------------------------
// Kernel 5: V accumulate, float4 loads. grid (NCHUNK, BB), 128 threads=4 warps.
// Warp w handles rows l = w+4i; lane owns e-quad. Cross-warp reduce in smem.
// ---------------------------------------------------------------------------
__global__ void k_vacc(const float* __restrict__ V) {
    int c = blockIdx.x, b = blockIdx.y;
    int tid = threadIdx.x, w = tid >> 5, lane = tid & 31;
    int l0 = c * LCHUNK;

    __shared__ float4 w4s[LCHUNK];
    __shared__ float4 sred[4][HH][32];
    {
        float4 m4;
        m4.x = decf(g_maxbits[b * HH + 0]);
        m4.y = decf(g_maxbits[b * HH + 1]);
        m4.z = decf(g_maxbits[b * HH + 2]);
        m4.w = decf(g_maxbits[b * HH + 3]);
        float4 s4 = g_s[(size_t)b * LL + l0 + tid];
        w4s[tid] = make_float4(__expf(s4.x - m4.x), __expf(s4.y - m4.y),
                               __expf(s4.z - m4.z), __expf(s4.w - m4.w));
    }
    __syncthreads();

    float4 a0 = make_float4(0,0,0,0), a1 = a0, a2 = a0, a3 = a0;
    const float* Vb = V + ((size_t)b * LL + l0) * DVV + lane * 4;
#pragma unroll 8
    for (int i = 0; i < 32; i++) {
        int l = w + i * 4;
        float4 v  = *(const float4*)(Vb + (size_t)l * DVV);
        float4 wl = w4s[l];
        a0.x += wl.x * v.x; a0.y += wl.x * v.y; a0.z += wl.x * v.z; a0.w += wl.x * v.w;
        a1.x += wl.y * v.x; a1.y += wl.y * v.y; a1.z += wl.y * v.z; a1.w += wl.y * v.w;
        a2.x += wl.z * v.x; a2.y += wl.z * v.y; a2.z += wl.z * v.z; a2.w += wl.z * v.w;
        a3.x += wl.w * v.x; a3.y += wl.w * v.y; a3.z += wl.w * v.z; a3.w += wl.w * v.w;
    }
    sred[w][0][lane] = a0;
    sred[w][1][lane] = a1;
    sred[w][2][lane] = a2;
    sred[w][3][lane] = a3;
    __syncthreads();

    int h = tid >> 5;            // reuse tid as (h, lane)
    float4 t  = sred[0][h][lane];
    float4 t1 = sred[1][h][lane];
    float4 t2 = sred[2][h][lane];
    float4 t3 = sred[3][h][lane];
    t.x += t1.x + t2.x + t3.x;
    t.y += t1.y + t2.y + t3.y;
    t.z += t1.z + t2.z + t3.z;
    t.w += t1.w + t2.w + t3.w;
    ((float4*)g_tp)[((size_t)(c * BB + b) * HH + h) * 32 + lane] = t;
}

// ---------------------------------------------------------------------------
// Kernel 6: merge sum partials, reduce chunk partials, contract with M.
// ---------------------------------------------------------------------------
__global__ void k_out(float* __restrict__ out) {
    int b = blockIdx.x;
    int tid = threadIdx.x;
    __shared__ float ts[HH * DVV];
    __shared__ float invs[HH];
    if (tid < HH) {
        float s = 0.f;
#pragma unroll
        for (int p = 0; p < NPART; p++) s += g_psum[(p * BB + b) * HH + tid];
        invs[tid] = 1.0f / s;
    }
    __syncthreads();
#pragma unroll
    for (int i = 0; i < 4; i++) {
        int idx = i * 128 + tid;
        int h = idx >> 7;
        float s = 0.f;
#pragma unroll 8
        for (int c = 0; c < NCHUNK; c++)
            s += g_tp[(size_t)(c * BB + b) * HH * DVV + idx];
        ts[idx] = s * invs[h];
    }
    __syncthreads();
    float acc = 0.f;
#pragma unroll 16
    for (int he = 0; he < HH * DVV; he++)
        acc += ts[he] * g_M[(size_t)he * RR + tid];
    out[b * RR + tid] = acc * (1.0f / LL);
}

// ---------------------------------------------------------------------------
extern "C" void kernel_launch(void* const* d_in, const int* in_sizes, int n_in,
                              void* d_out, int out_size) {
    const float* K  = (const float*)d_in[0];
    const float* V  = (const float*)d_in[1];
    const void*  mk = d_in[2];
    const float* Wq = (const float*)d_in[3];
    const float* Wk = (const float*)d_in[4];
    const float* Wv = (const float*)d_in[5];
    const float* Wo = (const float*)d_in[6];
    float* out = (float*)d_out;

    k_init<<<1, 256>>>((const unsigned int*)mk);
    k_prep_q<<<1, 512>>>(Wq, Wk);
    k_prep_M<<<HH * DVV, 128>>>(Wv, Wo);
    k_scores<<<BB * LL / 16, 256>>>(K, mk);
    k_sumexp<<<dim3(NPART, BB), 256>>>();
    k_vacc<<<dim3(NCHUNK, BB), 128>>>(V);
    k_out<<<BB, 128>>>(out);
}